// round 2
// baseline (speedup 1.0000x reference)
#include <cuda_runtime.h>

// m3_KDLoss: B=2048 rows, C=16384 cols, G=8 targets per row at base = row*G.
// loss = (1/B) * sum_{b,i} teacher[b,i] * ( lse_i(b) - v_i(b) )
// lse_i excludes the row's first i target columns; computed via a single
// (max, sumexp) pass + prefix subtraction of exp(v_j - M) terms.

#define NB   2048
#define NC   16384
#define GS   8
#define TPB  512
#define VPT  (NC / (TPB * 4))   // 8 float4 per thread

__device__ float g_row_loss[NB];

__global__ __launch_bounds__(TPB)
void kd_row_kernel(const float* __restrict__ S, const float* __restrict__ T)
{
    const int row = blockIdx.x;
    const int tid = threadIdx.x;
    const float4* Sr = reinterpret_cast<const float4*>(S + (size_t)row * NC);

    // ---- Load whole row into registers (front-batched LDG.128), per-thread max ----
    float4 v[VPT];
    float m = -3.402823466e+38f;
#pragma unroll
    for (int k = 0; k < VPT; k++) {
        v[k] = Sr[tid + k * TPB];
        m = fmaxf(m, fmaxf(fmaxf(v[k].x, v[k].y), fmaxf(v[k].z, v[k].w)));
    }

    __shared__ float red[TPB / 32];

    // block max reduction
#pragma unroll
    for (int o = 16; o; o >>= 1)
        m = fmaxf(m, __shfl_xor_sync(0xffffffffu, m, o));
    if ((tid & 31) == 0) red[tid >> 5] = m;
    __syncthreads();
    float M;
    {
        float mm = red[0];
#pragma unroll
        for (int w = 1; w < TPB / 32; w++) mm = fmaxf(mm, red[w]);
        M = mm;
    }
    __syncthreads();   // red[] reused below

    // ---- Sum of exp(x - M) from registers ----
    float s = 0.0f;
#pragma unroll
    for (int k = 0; k < VPT; k++) {
        s += __expf(v[k].x - M);
        s += __expf(v[k].y - M);
        s += __expf(v[k].z - M);
        s += __expf(v[k].w - M);
    }
#pragma unroll
    for (int o = 16; o; o >>= 1)
        s += __shfl_xor_sync(0xffffffffu, s, o);
    if ((tid & 31) == 0) red[tid >> 5] = s;
    __syncthreads();

    // ---- Sequential G-step epilogue (thread 0) ----
    if (tid == 0) {
        float tot = 0.0f;
#pragma unroll
        for (int w = 0; w < TPB / 32; w++) tot += red[w];

        const float* vbase = S + (size_t)row * NC + (size_t)row * GS; // target cols
        const float* tt    = T + (size_t)row * GS;

        float rem  = tot;    // sum of exp over currently-unmasked set
        float loss = 0.0f;
#pragma unroll
        for (int i = 0; i < GS; i++) {
            float vi  = vbase[i];
            float lse = M + __logf(rem);
            loss += tt[i] * (lse - vi);
            rem  -= __expf(vi - M);          // mask for subsequent steps
        }
        g_row_loss[row] = loss;
    }
}

__global__ __launch_bounds__(256)
void kd_reduce_kernel(float* __restrict__ out)
{
    __shared__ float red[8];
    float s = 0.0f;
    for (int i = threadIdx.x; i < NB; i += 256) s += g_row_loss[i];
#pragma unroll
    for (int o = 16; o; o >>= 1)
        s += __shfl_xor_sync(0xffffffffu, s, o);
    if ((threadIdx.x & 31) == 0) red[threadIdx.x >> 5] = s;
    __syncthreads();
    if (threadIdx.x == 0) {
        float tot = 0.0f;
#pragma unroll
        for (int w = 0; w < 8; w++) tot += red[w];
        out[0] = tot * (1.0f / (float)NB);
    }
}

extern "C" void kernel_launch(void* const* d_in, const int* in_sizes, int n_in,
                              void* d_out, int out_size)
{
    const float* S = (const float*)d_in[0];   // student_scores [B, C]
    const float* T = (const float*)d_in[1];   // teacher_targets [B, G]
    (void)in_sizes; (void)n_in; (void)out_size;

    kd_row_kernel<<<NB, TPB>>>(S, T);
    kd_reduce_kernel<<<1, 256>>>((float*)d_out);
}